// round 11
// baseline (speedup 1.0000x reference)
#include <cuda_runtime.h>
#include <cstdint>
#include <mma.h>

using namespace nvcuda;

// ---------------------------------------------------------------------------
// SW-MSA on GB300 (compute_103-portable).
// GEMMs: wmma m16n16k8 tf32, 3-stage cp.async pipeline, 2 CTAs/SM.
// Operands pre-rounded to tf32 (cvt.rna) in prep passes -> no in-loop converts
// (MMA truncation of already-rounded values is identity; bit-identical result).
// Attention: fp32 SIMT per (window, head), register-resident softmax.
// ---------------------------------------------------------------------------

namespace {
constexpr int Dm  = 384;
constexpr int TDm = 1152;
constexpr int NHm = 8;
constexpr int HDm = 48;
constexpr int Vm  = 36;
constexpr int GWm = 2048;
constexpr int Tm  = 73728;
constexpr float ATT_SCALE = 0.14433756729740643f;   // 48^-0.5

constexpr int NCH  = 12;        // K chunks of 32 (K = 384)
constexpr int ALD  = 36;        // A stage ld: 128 x 36
constexpr int BLD  = 132;       // B stage ld: 32 x 132
constexpr int CLD  = 132;       // C smem tile ld: 128 x 132
constexpr int AST  = 128 * ALD;             // 4608 floats
constexpr int BST  = 32 * BLD;              // 4224 floats
constexpr int STG  = AST + BST;             // 8832 floats per stage
constexpr int NSTG = 3;
constexpr int SMEM_BYTES = NSTG * STG * 4;  // 105984 B (C tile reuses it)
constexpr size_t PARTsz = (size_t)GWm * NHm * Vm * HDm;
}

// static device scratch (allocation-free per harness rules)
__device__ float g_xr[(size_t)Tm * Dm];             // tf32-rounded x
__device__ float g_wq[(size_t)384 * TDm];           // tf32-rounded w_qkv
__device__ float g_wp[(size_t)384 * Dm];            // tf32-rounded w_proj
__device__ float g_qkv[3 * PARTsz];                 // [part][win][head][v][hd]
__device__ float g_att[(size_t)Tm * Dm];            // attn out (tf32-rounded)

// ---------------- helpers ----------------
__device__ __forceinline__ uint32_t smem_u32(const void* p) {
    uint32_t a;
    asm("{ .reg .u64 t; cvta.to.shared.u64 t, %1; cvt.u32.u64 %0, t; }"
        : "=r"(a) : "l"(p));
    return a;
}
__device__ __forceinline__ float tf32r(float v) {
    uint32_t r;
    asm("cvt.rna.tf32.f32 %0, %1;" : "=r"(r) : "f"(v));
    return __uint_as_float(r);
}
__device__ __forceinline__ void cpa16(uint32_t dst, const void* src) {
    asm volatile("cp.async.cg.shared.global [%0], [%1], 16;" :: "r"(dst), "l"(src));
}
__device__ __forceinline__ size_t gather_off(int m) {   // roll(-3,-3) + win partition
    int gw = m / 36, v = m - gw * 36;
    int b  = gw >> 6, wi = gw & 63;
    int wh = wi >> 3, ww = wi & 7;
    int vh = v / 6,  vw = v - vh * 6;
    int sh = wh * 6 + vh + 3; if (sh >= 48) sh -= 48;
    int sw = ww * 6 + vw + 3; if (sw >= 48) sw -= 48;
    return (size_t)((b * 48 + sh) * 48 + sw) * Dm;
}

// ---------------------------------------------------------------------------
// prep: elementwise tf32 rounding (float4 grid-stride)
// ---------------------------------------------------------------------------
__global__ __launch_bounds__(256) void prep_round(const float4* __restrict__ src,
                                                  float4* __restrict__ dst, int n4)
{
    int i = blockIdx.x * 256 + threadIdx.x;
    if (i < n4) {
        float4 v = src[i];
        v.x = tf32r(v.x); v.y = tf32r(v.y); v.z = tf32r(v.z); v.w = tf32r(v.w);
        dst[i] = v;
    }
}

// ---------------------------------------------------------------------------
// wmma tf32 GEMM. CTA tile 128x128, 8 warps in 2(m) x 4(n), warp tile 64x32.
// 3-stage cp.async pipeline; 2 CTAs/SM. Operands pre-rounded -> no converts.
// MODE 0: A = g_xr with roll/window gather, W = g_wq -> scatter into g_qkv.
// MODE 1: A = g_att (row-major),            W = g_wp -> row-major into outp.
// ---------------------------------------------------------------------------
template<int MODE>
__global__ __launch_bounds__(256, 2) void gemm_wmma(const float* __restrict__ bias,
                                                    float* __restrict__ outp, int N)
{
    extern __shared__ float sm[];
    const int t = threadIdx.x, wid = t >> 5;
    const int wm = wid >> 2, wn = wid & 3;        // 2 x 4 warp grid
    const int mt = blockIdx.y, nt = blockIdx.x;

    const float* Abase = (MODE == 0) ? g_xr : g_att;
    const float* W     = (MODE == 0) ? g_wq : g_wp;

    // ---- staging assignments (fixed per thread) ----
    const int ar = t >> 1, ah = (t & 1) * 16;     // A: 2 threads/row, 16 floats each
    size_t aoff = (MODE == 0) ? gather_off(mt * 128 + ar)
                              : (size_t)(mt * 128 + ar) * Dm;
    const float* asrc = Abase + aoff + ah;
    const int bk = t >> 3, bs = (t & 7) * 16;     // B: 8 threads/row, 16 floats each
    const float* bsrc = W + (size_t)bk * N + nt * 128 + bs;

    const uint32_t sa0 = smem_u32(sm + ar * ALD + ah);
    const uint32_t sb0 = smem_u32(sm + AST + bk * BLD + bs);

    auto stage_cp = [&](int c, int s) {
        uint32_t sa = sa0 + (uint32_t)s * (STG * 4);
        uint32_t sb = sb0 + (uint32_t)s * (STG * 4);
        const float* ap = asrc + c * 32;
        const float* bp = bsrc + (size_t)c * 32 * N;
#pragma unroll
        for (int j = 0; j < 4; ++j) {
            cpa16(sa + j * 16u, ap + j * 4);
            cpa16(sb + j * 16u, bp + j * 4);
        }
        asm volatile("cp.async.commit_group;");
    };

    wmma::fragment<wmma::accumulator, 16, 16, 8, float> acc[4][2];
#pragma unroll
    for (int mi = 0; mi < 4; ++mi)
#pragma unroll
        for (int nj = 0; nj < 2; ++nj)
            wmma::fill_fragment(acc[mi][nj], 0.0f);

    stage_cp(0, 0);
    stage_cp(1, 1);

    int s_cur = 0, s_pf = 2;   // rolling stage indices (mod 3)
    for (int c = 0; c < NCH; ++c) {
        if (c + 2 < NCH) {
            stage_cp(c + 2, s_pf);
            if (++s_pf == NSTG) s_pf = 0;
            asm volatile("cp.async.wait_group 2;" ::: "memory");
        } else if (c + 1 < NCH) {
            asm volatile("cp.async.wait_group 1;" ::: "memory");
        } else {
            asm volatile("cp.async.wait_group 0;" ::: "memory");
        }
        __syncthreads();

        const float* As = sm + s_cur * STG;
        const float* Bs = As + AST;
        if (++s_cur == NSTG) s_cur = 0;
#pragma unroll
        for (int ks = 0; ks < 4; ++ks) {
            wmma::fragment<wmma::matrix_a, 16, 16, 8, wmma::precision::tf32,
                           wmma::row_major> af[4];
            wmma::fragment<wmma::matrix_b, 16, 16, 8, wmma::precision::tf32,
                           wmma::row_major> bf[2];
#pragma unroll
            for (int mi = 0; mi < 4; ++mi)
                wmma::load_matrix_sync(af[mi],
                    As + (wm * 64 + mi * 16) * ALD + ks * 8, ALD);
#pragma unroll
            for (int nj = 0; nj < 2; ++nj)
                wmma::load_matrix_sync(bf[nj],
                    Bs + (ks * 8) * BLD + wn * 32 + nj * 16, BLD);
            // operands pre-rounded to tf32 -> no per-element conversion needed
#pragma unroll
            for (int mi = 0; mi < 4; ++mi)
#pragma unroll
                for (int nj = 0; nj < 2; ++nj)
                    wmma::mma_sync(acc[mi][nj], af[mi], bf[nj], acc[mi][nj]);
        }
        __syncthreads();
    }

    // ---- epilogue: C -> SMEM, then generic scatter ----
    float* Cs = sm;
#pragma unroll
    for (int mi = 0; mi < 4; ++mi)
#pragma unroll
        for (int nj = 0; nj < 2; ++nj)
            wmma::store_matrix_sync(Cs + (wm * 64 + mi * 16) * CLD + wn * 32 + nj * 16,
                                    acc[mi][nj], CLD, wmma::mem_row_major);
    __syncthreads();

    for (int f = t; f < 128 * 32; f += 256) {        // 128 rows x 32 float4-cols
        int r  = f >> 5;
        int c4 = (f & 31) * 4;
        float4 v = *reinterpret_cast<const float4*>(Cs + r * CLD + c4);
        int n = nt * 128 + c4;
        v.x += bias[n];  v.y += bias[n + 1];  v.z += bias[n + 2];  v.w += bias[n + 3];
        int m = mt * 128 + r;
        if (MODE == 1) {
            *reinterpret_cast<float4*>(outp + (size_t)m * Dm + n) = v;
        } else {
            int gw = m / 36, vv = m - gw * 36;
            int part = n / 384;
            int pr   = n - part * 384;
            int head = pr / 48, hd = pr - head * 48;
            *reinterpret_cast<float4*>(g_qkv + (size_t)part * PARTsz
                                       + (size_t)gw * (NHm * Vm * HDm)
                                       + (size_t)head * (Vm * HDm)
                                       + (size_t)vv * HDm + hd) = v;
        }
    }
}

// ---------------------------------------------------------------------------
// Attention per (window, head). Scores in registers through softmax;
// scale folded into q at SMEM load; output tf32-rounded for proj GEMM.
// ---------------------------------------------------------------------------
__global__ __launch_bounds__(256) void attn_kernel()
{
    __shared__ float qs[36][49];
    __shared__ float ks[36][49];
    __shared__ float vs[36][49];
    __shared__ float sc[36][37];
    __shared__ float pmx[36][6];
    __shared__ float psum[36][6];
    __shared__ float rmax[36];
    __shared__ float rinv[36];
    __shared__ int   rid[36];

    const int t    = threadIdx.x;
    const int gw   = blockIdx.x >> 3;
    const int head = blockIdx.x & 7;

    const float* gq = g_qkv + (size_t)gw * (NHm * Vm * HDm) + (size_t)head * (Vm * HDm);
    const float* gk = gq + PARTsz;
    const float* gv = gq + 2 * PARTsz;

    for (int idx = t; idx < Vm * HDm; idx += 256) {
        int i = idx / 48, d = idx - i * 48;
        qs[i][d] = gq[idx] * ATT_SCALE;
        ks[i][d] = gk[idx];
        vs[i][d] = gv[idx];
    }
    const int wi = gw & 63;
    const int wh = wi >> 3, ww = wi & 7;
    if (t < 36) {
        int vh = t / 6, vw = t - vh * 6;
        int y  = wh * 6 + vh + 3; if (y  >= 48) y  -= 48;
        int xq = ww * 6 + vw + 3; if (xq >= 48) xq -= 48;
        rid[t] = ((y >= 3) ? 2 : 0) + ((xq >= 3) ? 1 : 0);
    }
    __syncthreads();

    const int i  = t / 6;            // row (valid when t < 216)
    const int jg = t - i * 6;        // 6-col group
    const int j0 = jg * 6;
    float acc[6];

    if (t < 216) {
#pragma unroll
        for (int jj = 0; jj < 6; ++jj) acc[jj] = 0.f;
#pragma unroll 4
        for (int kx = 0; kx < 48; ++kx) {
            float qv = qs[i][kx];
#pragma unroll
            for (int jj = 0; jj < 6; ++jj)
                acc[jj] += qv * ks[j0 + jj][kx];
        }
        int ri = rid[i];
        float m6 = -3.4e38f;
#pragma unroll
        for (int jj = 0; jj < 6; ++jj) {
            float val = acc[jj];
            if (rid[j0 + jj] != ri) val = -1e30f;
            acc[jj] = val;
            m6 = fmaxf(m6, val);
        }
        pmx[i][jg] = m6;
    }
    __syncthreads();

    if (t < 36) {
        float m = pmx[t][0];
#pragma unroll
        for (int g = 1; g < 6; ++g) m = fmaxf(m, pmx[t][g]);
        rmax[t] = m;
    }
    __syncthreads();

    if (t < 216) {
        float m = rmax[i], s = 0.f;
#pragma unroll
        for (int jj = 0; jj < 6; ++jj) {
            acc[jj] = __expf(acc[jj] - m);
            s += acc[jj];
        }
        psum[i][jg] = s;
    }
    __syncthreads();

    if (t < 36) {
        float s = psum[t][0];
#pragma unroll
        for (int g = 1; g < 6; ++g) s += psum[t][g];
        rinv[t] = 1.f / s;
    }
    __syncthreads();

    if (t < 216) {
        float inv = rinv[i];
#pragma unroll
        for (int jj = 0; jj < 6; ++jj) sc[i][j0 + jj] = acc[jj] * inv;
    }
    __syncthreads();

    if (t < 216) {
        const int d0 = jg * 8;
        float av[8] = {0.f, 0.f, 0.f, 0.f, 0.f, 0.f, 0.f, 0.f};
#pragma unroll 4
        for (int j = 0; j < 36; ++j) {
            float sv = sc[i][j];
#pragma unroll
            for (int dd = 0; dd < 8; ++dd)
                av[dd] += sv * vs[j][d0 + dd];
        }
        int b  = gw >> 6;
        int vh = i / 6, vw = i - vh * 6;
        int dh = wh * 6 + vh + 3; if (dh >= 48) dh -= 48;   // reverse + roll(+3)
        int dw = ww * 6 + vw + 3; if (dw >= 48) dw -= 48;
        size_t o = ((size_t)(b * 48 + dh) * 48 + dw) * Dm + head * HDm + d0;
#pragma unroll
        for (int dd = 0; dd < 8; ++dd) g_att[o + dd] = tf32r(av[dd]);
    }
}

// ---------------------------------------------------------------------------
extern "C" void kernel_launch(void* const* d_in, const int* in_sizes, int n_in,
                              void* d_out, int out_size)
{
    const float* x     = (const float*)d_in[0];
    const float* wqkv  = (const float*)d_in[1];
    const float* bqkv  = (const float*)d_in[2];
    const float* wproj = (const float*)d_in[3];
    const float* bproj = (const float*)d_in[4];
    float* out = (float*)d_out;

    float* s_xr; float* s_wq; float* s_wp;
    cudaGetSymbolAddress((void**)&s_xr, g_xr);
    cudaGetSymbolAddress((void**)&s_wq, g_wq);
    cudaGetSymbolAddress((void**)&s_wp, g_wp);
    cudaFuncSetAttribute(gemm_wmma<0>, cudaFuncAttributeMaxDynamicSharedMemorySize, SMEM_BYTES);
    cudaFuncSetAttribute(gemm_wmma<1>, cudaFuncAttributeMaxDynamicSharedMemorySize, SMEM_BYTES);

    const int nx = Tm * Dm / 4, nwq = 384 * TDm / 4, nwp = 384 * Dm / 4;
    prep_round<<<(nx  + 255) / 256, 256>>>((const float4*)x,     (float4*)s_xr, nx);
    prep_round<<<(nwq + 255) / 256, 256>>>((const float4*)wqkv,  (float4*)s_wq, nwq);
    prep_round<<<(nwp + 255) / 256, 256>>>((const float4*)wproj, (float4*)s_wp, nwp);

    gemm_wmma<0><<<dim3(9, 576), 256, SMEM_BYTES>>>(bqkv, nullptr, TDm);
    attn_kernel<<<GWm * NHm, 256>>>();
    gemm_wmma<1><<<dim3(3, 576), 256, SMEM_BYTES>>>(bproj, out, Dm);
}

// round 13
// speedup vs baseline: 1.1226x; 1.1226x over previous
#include <cuda_runtime.h>
#include <cstdint>
#include <mma.h>

using namespace nvcuda;

// ---------------------------------------------------------------------------
// SW-MSA on GB300 (compute_103-portable).
// GEMMs: wmma m16n16k8 tf32 (R10-proven: in-loop converts, 3-stage cp.async,
// 2 CTAs/SM). Attention: ALSO wmma tf32 — per (window,head), pad 36->48,
// S = Q*K^T and O = S*V as 9 warp-tiles x 6 k-steps each.
// ---------------------------------------------------------------------------

namespace {
constexpr int Dm  = 384;
constexpr int TDm = 1152;
constexpr int NHm = 8;
constexpr int HDm = 48;
constexpr int Vm  = 36;
constexpr int GWm = 2048;
constexpr int Tm  = 73728;
constexpr float ATT_SCALE = 0.14433756729740643f;   // 48^-0.5

constexpr int NCH  = 12;        // K chunks of 32 (K = 384)
constexpr int ALD  = 36;
constexpr int BLD  = 132;
constexpr int CLD  = 132;
constexpr int AST  = 128 * ALD;
constexpr int BST  = 32 * BLD;
constexpr int STG  = AST + BST;
constexpr int NSTG = 3;
constexpr int SMEM_BYTES = NSTG * STG * 4;
constexpr size_t PARTsz = (size_t)GWm * NHm * Vm * HDm;

constexpr int SLD = 52;         // attn smem ld (48 + pad, 16B-multiple)
}

// static device scratch (allocation-free per harness rules)
__device__ float g_qkv[3 * PARTsz];                 // [part][win][head][v][hd]
__device__ float g_att[(size_t)Tm * Dm];            // attn out, row-major [token][D]

// ---------------- helpers ----------------
__device__ __forceinline__ uint32_t smem_u32(const void* p) {
    uint32_t a;
    asm("{ .reg .u64 t; cvta.to.shared.u64 t, %1; cvt.u32.u64 %0, t; }"
        : "=r"(a) : "l"(p));
    return a;
}
__device__ __forceinline__ float tf32r(float v) {
    uint32_t r;
    asm("cvt.rna.tf32.f32 %0, %1;" : "=r"(r) : "f"(v));
    return __uint_as_float(r);
}
__device__ __forceinline__ void cpa16(uint32_t dst, const void* src) {
    asm volatile("cp.async.cg.shared.global [%0], [%1], 16;" :: "r"(dst), "l"(src));
}
__device__ __forceinline__ size_t gather_off(int m) {   // roll(-3,-3) + win partition
    int gw = m / 36, v = m - gw * 36;
    int b  = gw >> 6, wi = gw & 63;
    int wh = wi >> 3, ww = wi & 7;
    int vh = v / 6,  vw = v - vh * 6;
    int sh = wh * 6 + vh + 3; if (sh >= 48) sh -= 48;
    int sw = ww * 6 + vw + 3; if (sw >= 48) sw -= 48;
    return (size_t)((b * 48 + sh) * 48 + sw) * Dm;
}

// ---------------------------------------------------------------------------
// wmma tf32 GEMM (R10-proven). CTA 128x128, 8 warps 2x4, warp tile 64x32.
// ---------------------------------------------------------------------------
template<int MODE>
__global__ __launch_bounds__(256, 2) void gemm_wmma(const float* __restrict__ Ain,
                                                    const float* __restrict__ W,
                                                    const float* __restrict__ bias,
                                                    float* __restrict__ outp, int N)
{
    extern __shared__ float sm[];
    const int t = threadIdx.x, wid = t >> 5;
    const int wm = wid >> 2, wn = wid & 3;
    const int mt = blockIdx.y, nt = blockIdx.x;

    const float* Abase = (MODE == 0) ? Ain : g_att;

    const int ar = t >> 1, ah = (t & 1) * 16;
    size_t aoff = (MODE == 0) ? gather_off(mt * 128 + ar)
                              : (size_t)(mt * 128 + ar) * Dm;
    const float* asrc = Abase + aoff + ah;
    const int bk = t >> 3, bs = (t & 7) * 16;
    const float* bsrc = W + (size_t)bk * N + nt * 128 + bs;

    const uint32_t sa0 = smem_u32(sm + ar * ALD + ah);
    const uint32_t sb0 = smem_u32(sm + AST + bk * BLD + bs);

    auto stage_cp = [&](int c, int s) {
        uint32_t sa = sa0 + (uint32_t)s * (STG * 4);
        uint32_t sb = sb0 + (uint32_t)s * (STG * 4);
        const float* ap = asrc + c * 32;
        const float* bp = bsrc + (size_t)c * 32 * N;
#pragma unroll
        for (int j = 0; j < 4; ++j) {
            cpa16(sa + j * 16u, ap + j * 4);
            cpa16(sb + j * 16u, bp + j * 4);
        }
        asm volatile("cp.async.commit_group;");
    };

    wmma::fragment<wmma::accumulator, 16, 16, 8, float> acc[4][2];
#pragma unroll
    for (int mi = 0; mi < 4; ++mi)
#pragma unroll
        for (int nj = 0; nj < 2; ++nj)
            wmma::fill_fragment(acc[mi][nj], 0.0f);

    stage_cp(0, 0);
    stage_cp(1, 1);

    int s_cur = 0, s_pf = 2;
    for (int c = 0; c < NCH; ++c) {
        if (c + 2 < NCH) {
            stage_cp(c + 2, s_pf);
            if (++s_pf == NSTG) s_pf = 0;
            asm volatile("cp.async.wait_group 2;" ::: "memory");
        } else if (c + 1 < NCH) {
            asm volatile("cp.async.wait_group 1;" ::: "memory");
        } else {
            asm volatile("cp.async.wait_group 0;" ::: "memory");
        }
        __syncthreads();

        const float* As = sm + s_cur * STG;
        const float* Bs = As + AST;
        if (++s_cur == NSTG) s_cur = 0;
#pragma unroll
        for (int ks = 0; ks < 4; ++ks) {
            wmma::fragment<wmma::matrix_a, 16, 16, 8, wmma::precision::tf32,
                           wmma::row_major> af[4];
            wmma::fragment<wmma::matrix_b, 16, 16, 8, wmma::precision::tf32,
                           wmma::row_major> bf[2];
#pragma unroll
            for (int mi = 0; mi < 4; ++mi) {
                wmma::load_matrix_sync(af[mi],
                    As + (wm * 64 + mi * 16) * ALD + ks * 8, ALD);
#pragma unroll
                for (int e = 0; e < af[mi].num_elements; ++e)
                    af[mi].x[e] = wmma::__float_to_tf32(af[mi].x[e]);
            }
#pragma unroll
            for (int nj = 0; nj < 2; ++nj) {
                wmma::load_matrix_sync(bf[nj],
                    Bs + (ks * 8) * BLD + wn * 32 + nj * 16, BLD);
#pragma unroll
                for (int e = 0; e < bf[nj].num_elements; ++e)
                    bf[nj].x[e] = wmma::__float_to_tf32(bf[nj].x[e]);
            }
#pragma unroll
            for (int mi = 0; mi < 4; ++mi)
#pragma unroll
                for (int nj = 0; nj < 2; ++nj)
                    wmma::mma_sync(acc[mi][nj], af[mi], bf[nj], acc[mi][nj]);
        }
        __syncthreads();
    }

    float* Cs = sm;
#pragma unroll
    for (int mi = 0; mi < 4; ++mi)
#pragma unroll
        for (int nj = 0; nj < 2; ++nj)
            wmma::store_matrix_sync(Cs + (wm * 64 + mi * 16) * CLD + wn * 32 + nj * 16,
                                    acc[mi][nj], CLD, wmma::mem_row_major);
    __syncthreads();

    for (int f = t; f < 128 * 32; f += 256) {
        int r  = f >> 5;
        int c4 = (f & 31) * 4;
        float4 v = *reinterpret_cast<const float4*>(Cs + r * CLD + c4);
        int n = nt * 128 + c4;
        v.x += bias[n];  v.y += bias[n + 1];  v.z += bias[n + 2];  v.w += bias[n + 3];
        int m = mt * 128 + r;
        if (MODE == 1) {
            *reinterpret_cast<float4*>(outp + (size_t)m * Dm + n) = v;
        } else {
            int gw = m / 36, vv = m - gw * 36;
            int part = n / 384;
            int pr   = n - part * 384;
            int head = pr / 48, hd = pr - head * 48;
            *reinterpret_cast<float4*>(g_qkv + (size_t)part * PARTsz
                                       + (size_t)gw * (NHm * Vm * HDm)
                                       + (size_t)head * (Vm * HDm)
                                       + (size_t)vv * HDm + hd) = v;
        }
    }
}

// ---------------------------------------------------------------------------
// Attention per (window, head) via wmma tf32, padded 36->48.
// Zero-padded Q rows / K cols / V rows make pad regions exact zeros, so the
// softmax & mask logic only touches the real 36x36 block.
// ---------------------------------------------------------------------------
__global__ __launch_bounds__(256) void attn_wmma()
{
    __shared__ __align__(16) float qs [48][SLD];   // Q [tok][hd]; later reused for O
    __shared__ __align__(16) float kst[48][SLD];   // K^T [hd][tok]
    __shared__ __align__(16) float vs [48][SLD];   // V [tok][hd]
    __shared__ __align__(16) float ss [48][SLD];   // S, then probs
    __shared__ float pmx[36][6];
    __shared__ float psum[36][6];
    __shared__ float rmax[36];
    __shared__ float rinv[36];
    __shared__ int   rid[36];

    const int t    = threadIdx.x;
    const int wid  = t >> 5;
    const int gw   = blockIdx.x >> 3;
    const int head = blockIdx.x & 7;

    const float* gq = g_qkv + (size_t)gw * (NHm * Vm * HDm) + (size_t)head * (Vm * HDm);
    const float* gk = gq + PARTsz;
    const float* gv = gq + 2 * PARTsz;

    // zero pads (full arrays; fills below overwrite the live region)
    for (int idx = t; idx < 48 * SLD; idx += 256) {
        int r = idx / SLD, c2 = idx - r * SLD;
        qs[r][c2] = 0.f; kst[r][c2] = 0.f; vs[r][c2] = 0.f;
    }
    __syncthreads();

    for (int idx = t; idx < Vm * HDm; idx += 256) {
        int i = idx / 48, d = idx - i * 48;
        qs[i][d]  = tf32r(gq[idx] * ATT_SCALE);
        kst[d][i] = tf32r(gk[idx]);
        vs[i][d]  = tf32r(gv[idx]);
    }
    const int wi = gw & 63;
    const int wh = wi >> 3, ww = wi & 7;
    if (t < 36) {
        int vh = t / 6, vw = t - vh * 6;
        int y  = wh * 6 + vh + 3; if (y  >= 48) y  -= 48;
        int xq = ww * 6 + vw + 3; if (xq >= 48) xq -= 48;
        rid[t] = ((y >= 3) ? 2 : 0) + ((xq >= 3) ? 1 : 0);
    }
    __syncthreads();

    // ---- S = Q * K^T (48x48x48): 9 tiles over 8 warps ----
    for (int tile = wid; tile < 9; tile += 8) {
        int mi = tile / 3, ni = tile - mi * 3;
        wmma::fragment<wmma::accumulator, 16, 16, 8, float> sacc;
        wmma::fill_fragment(sacc, 0.0f);
#pragma unroll
        for (int kk = 0; kk < 6; ++kk) {
            wmma::fragment<wmma::matrix_a, 16, 16, 8, wmma::precision::tf32,
                           wmma::row_major> af;
            wmma::fragment<wmma::matrix_b, 16, 16, 8, wmma::precision::tf32,
                           wmma::row_major> bf;
            wmma::load_matrix_sync(af, &qs[mi * 16][kk * 8], SLD);
            wmma::load_matrix_sync(bf, &kst[kk * 8][ni * 16], SLD);
            wmma::mma_sync(sacc, af, bf, sacc);
        }
        wmma::store_matrix_sync(&ss[mi * 16][ni * 16], sacc, SLD, wmma::mem_row_major);
    }
    __syncthreads();

    // ---- mask + softmax on the 36x36 live block ----
    const int i  = t / 6;
    const int jg = t - i * 6;
    const int j0 = jg * 6;
    float acc[6];

    if (t < 216) {
        int ri = rid[i];
        float m6 = -3.4e38f;
#pragma unroll
        for (int jj = 0; jj < 6; ++jj) {
            float val = ss[i][j0 + jj];
            if (rid[j0 + jj] != ri) val = -1e30f;
            acc[jj] = val;
            m6 = fmaxf(m6, val);
        }
        pmx[i][jg] = m6;
    }
    __syncthreads();
    if (t < 36) {
        float m = pmx[t][0];
#pragma unroll
        for (int g = 1; g < 6; ++g) m = fmaxf(m, pmx[t][g]);
        rmax[t] = m;
    }
    __syncthreads();
    if (t < 216) {
        float m = rmax[i], s = 0.f;
#pragma unroll
        for (int jj = 0; jj < 6; ++jj) {
            acc[jj] = __expf(acc[jj] - m);
            s += acc[jj];
        }
        psum[i][jg] = s;
    }
    __syncthreads();
    if (t < 36) {
        float s = psum[t][0];
#pragma unroll
        for (int g = 1; g < 6; ++g) s += psum[t][g];
        rinv[t] = 1.f / s;
    }
    __syncthreads();
    if (t < 216) {
        float inv = rinv[i];
#pragma unroll
        for (int jj = 0; jj < 6; ++jj)
            ss[i][j0 + jj] = tf32r(acc[jj] * inv);   // pads stay exact 0
    }
    __syncthreads();

    // ---- O = S * V (48x48x48) into qs (reused) ----
    for (int tile = wid; tile < 9; tile += 8) {
        int mi = tile / 3, ni = tile - mi * 3;
        wmma::fragment<wmma::accumulator, 16, 16, 8, float> oacc;
        wmma::fill_fragment(oacc, 0.0f);
#pragma unroll
        for (int kk = 0; kk < 6; ++kk) {
            wmma::fragment<wmma::matrix_a, 16, 16, 8, wmma::precision::tf32,
                           wmma::row_major> af;
            wmma::fragment<wmma::matrix_b, 16, 16, 8, wmma::precision::tf32,
                           wmma::row_major> bf;
            wmma::load_matrix_sync(af, &ss[mi * 16][kk * 8], SLD);
            wmma::load_matrix_sync(bf, &vs[kk * 8][ni * 16], SLD);
            wmma::mma_sync(oacc, af, bf, oacc);
        }
        wmma::store_matrix_sync(&qs[mi * 16][ni * 16], oacc, SLD, wmma::mem_row_major);
    }
    __syncthreads();

    // ---- write out with reverse + roll(+3) ----
    if (t < 216) {
        const int d0 = jg * 8;
        int b  = gw >> 6;
        int vh = i / 6, vw = i - vh * 6;
        int dh = wh * 6 + vh + 3; if (dh >= 48) dh -= 48;
        int dw = ww * 6 + vw + 3; if (dw >= 48) dw -= 48;
        size_t o = ((size_t)(b * 48 + dh) * 48 + dw) * Dm + head * HDm + d0;
#pragma unroll
        for (int dd = 0; dd < 8; ++dd) g_att[o + dd] = qs[i][d0 + dd];
    }
}

// ---------------------------------------------------------------------------
extern "C" void kernel_launch(void* const* d_in, const int* in_sizes, int n_in,
                              void* d_out, int out_size)
{
    const float* x     = (const float*)d_in[0];
    const float* wqkv  = (const float*)d_in[1];
    const float* bqkv  = (const float*)d_in[2];
    const float* wproj = (const float*)d_in[3];
    const float* bproj = (const float*)d_in[4];
    float* out = (float*)d_out;

    cudaFuncSetAttribute(gemm_wmma<0>, cudaFuncAttributeMaxDynamicSharedMemorySize, SMEM_BYTES);
    cudaFuncSetAttribute(gemm_wmma<1>, cudaFuncAttributeMaxDynamicSharedMemorySize, SMEM_BYTES);

    gemm_wmma<0><<<dim3(9, 576), 256, SMEM_BYTES>>>(x, wqkv, bqkv, nullptr, TDm);
    attn_wmma<<<GWm * NHm, 256>>>();
    gemm_wmma<1><<<dim3(3, 576), 256, SMEM_BYTES>>>(nullptr, wproj, bproj, out, Dm);
}

// round 16
// speedup vs baseline: 2.6782x; 2.3858x over previous
#include <cuda_runtime.h>
#include <cuda_fp16.h>
#include <cstdint>
#include <mma.h>

using namespace nvcuda;

// ---------------------------------------------------------------------------
// SW-MSA on GB300 (compute_103-portable).
// GEMMs: wmma m16n16k16 FP16 (f32 accumulate) — fp16 mantissa == tf32 mantissa,
// 2x tensor rate, half the smem/L2 traffic, K-chunks of 64 (NCH=6).
// Attention: wmma tf32 per (window,head) (R13-proven), writes half for proj.
// ---------------------------------------------------------------------------

namespace {
constexpr int Dm  = 384;
constexpr int TDm = 1152;
constexpr int NHm = 8;
constexpr int HDm = 48;
constexpr int Vm  = 36;
constexpr int GWm = 2048;
constexpr int Tm  = 73728;
constexpr float ATT_SCALE = 0.14433756729740643f;   // 48^-0.5

constexpr int KCH  = 64;        // K per chunk (halfs)
constexpr int NCH  = 6;         // 384 / 64
constexpr int ALD  = 72;        // A stage ld in halfs (64 + 8 pad; 144B rows)
constexpr int BLD  = 136;       // B stage ld in halfs (128 + 8 pad; 272B rows)
constexpr int CLD  = 132;       // C smem tile ld (floats)
constexpr int AST  = 128 * ALD;             // 9216 halfs
constexpr int BST  = 64 * BLD;              // 8704 halfs
constexpr int STG  = AST + BST;             // 17920 halfs = 35840 B
constexpr int NSTG = 3;
constexpr int SMEM_BYTES = NSTG * STG * 2;  // 107520 B (C tile 67584 B reuses)
constexpr size_t PARTsz = (size_t)GWm * NHm * Vm * HDm;

constexpr int SLD = 52;         // attn smem ld (48 + pad)
}

// static device scratch (allocation-free per harness rules)
__device__ __half g_xh[(size_t)Tm * Dm];            // x as fp16
__device__ __half g_wqh[(size_t)384 * TDm];         // w_qkv as fp16
__device__ __half g_wph[(size_t)384 * Dm];          // w_proj as fp16
__device__ float  g_qkv[3 * PARTsz];                // [part][win][head][v][hd]
__device__ __half g_att[(size_t)Tm * Dm];           // attn out as fp16

// ---------------- helpers ----------------
__device__ __forceinline__ uint32_t smem_u32(const void* p) {
    uint32_t a;
    asm("{ .reg .u64 t; cvta.to.shared.u64 t, %1; cvt.u32.u64 %0, t; }"
        : "=r"(a) : "l"(p));
    return a;
}
__device__ __forceinline__ float tf32r(float v) {
    uint32_t r;
    asm("cvt.rna.tf32.f32 %0, %1;" : "=r"(r) : "f"(v));
    return __uint_as_float(r);
}
__device__ __forceinline__ void cpa16(uint32_t dst, const void* src) {
    asm volatile("cp.async.cg.shared.global [%0], [%1], 16;" :: "r"(dst), "l"(src));
}
__device__ __forceinline__ size_t gather_off(int m) {   // roll(-3,-3) + win partition
    int gw = m / 36, v = m - gw * 36;
    int b  = gw >> 6, wi = gw & 63;
    int wh = wi >> 3, ww = wi & 7;
    int vh = v / 6,  vw = v - vh * 6;
    int sh = wh * 6 + vh + 3; if (sh >= 48) sh -= 48;
    int sw = ww * 6 + vw + 3; if (sw >= 48) sw -= 48;
    return (size_t)((b * 48 + sh) * 48 + sw) * Dm;
}

// ---------------------------------------------------------------------------
// prep: f32 -> f16 (each thread converts 4 elements)
// ---------------------------------------------------------------------------
__global__ __launch_bounds__(256) void prep_half(const float4* __restrict__ src,
                                                 __half* __restrict__ dst, int n4)
{
    int i = blockIdx.x * 256 + threadIdx.x;
    if (i < n4) {
        float4 v = src[i];
        __half2* d2 = reinterpret_cast<__half2*>(dst + (size_t)i * 4);
        d2[0] = __floats2half2_rn(v.x, v.y);
        d2[1] = __floats2half2_rn(v.z, v.w);
    }
}

// ---------------------------------------------------------------------------
// wmma fp16 GEMM. CTA 128x128, 8 warps 2x4, warp tile 64x32, K chunks of 64,
// 3-stage cp.async, 2 CTAs/SM.
// MODE 0: A = g_xh (roll/window gather), W = g_wqh -> scatter into g_qkv (f32).
// MODE 1: A = g_att (row-major half),    W = g_wph -> row-major into outp.
// ---------------------------------------------------------------------------
template<int MODE>
__global__ __launch_bounds__(256, 2) void gemm_hmma(const float* __restrict__ bias,
                                                    float* __restrict__ outp, int N)
{
    extern __shared__ __half smh[];
    const int t = threadIdx.x, wid = t >> 5;
    const int wm = wid >> 2, wn = wid & 3;        // 2 x 4 warp grid
    const int mt = blockIdx.y, nt = blockIdx.x;

    const __half* Abase = (MODE == 0) ? g_xh : g_att;
    const __half* W     = (MODE == 0) ? g_wqh : g_wph;

    // A staging: 2 threads/row, 64 B (32 halfs) each
    const int ar = t >> 1, ah = (t & 1) * 32;
    size_t aoff = (MODE == 0) ? gather_off(mt * 128 + ar)
                              : (size_t)(mt * 128 + ar) * Dm;
    const __half* asrc = Abase + aoff + ah;
    // B staging: 4 threads/row (64 rows), 64 B (32 halfs) each
    const int bk = t >> 2, bs = (t & 3) * 32;
    const __half* bsrc = W + (size_t)bk * N + nt * 128 + bs;

    const uint32_t sa0 = smem_u32(smh + ar * ALD + ah);
    const uint32_t sb0 = smem_u32(smh + AST + bk * BLD + bs);

    auto stage_cp = [&](int c, int s) {
        uint32_t sa = sa0 + (uint32_t)s * (STG * 2);
        uint32_t sb = sb0 + (uint32_t)s * (STG * 2);
        const __half* ap = asrc + c * KCH;
        const __half* bp = bsrc + (size_t)c * KCH * N;
#pragma unroll
        for (int j = 0; j < 4; ++j) {
            cpa16(sa + j * 16u, ap + j * 8);
            cpa16(sb + j * 16u, bp + j * 8);
        }
        asm volatile("cp.async.commit_group;");
    };

    wmma::fragment<wmma::accumulator, 16, 16, 16, float> acc[4][2];
#pragma unroll
    for (int mi = 0; mi < 4; ++mi)
#pragma unroll
        for (int nj = 0; nj < 2; ++nj)
            wmma::fill_fragment(acc[mi][nj], 0.0f);

    stage_cp(0, 0);
    stage_cp(1, 1);

    int s_cur = 0, s_pf = 2;
    for (int c = 0; c < NCH; ++c) {
        if (c + 2 < NCH) {
            stage_cp(c + 2, s_pf);
            if (++s_pf == NSTG) s_pf = 0;
            asm volatile("cp.async.wait_group 2;" ::: "memory");
        } else if (c + 1 < NCH) {
            asm volatile("cp.async.wait_group 1;" ::: "memory");
        } else {
            asm volatile("cp.async.wait_group 0;" ::: "memory");
        }
        __syncthreads();

        const __half* As = smh + s_cur * STG;
        const __half* Bs = As + AST;
        if (++s_cur == NSTG) s_cur = 0;
#pragma unroll
        for (int ks = 0; ks < 4; ++ks) {      // 4 k-steps of 16
            wmma::fragment<wmma::matrix_b, 16, 16, 16, __half, wmma::row_major> bf[2];
#pragma unroll
            for (int nj = 0; nj < 2; ++nj)
                wmma::load_matrix_sync(bf[nj],
                    Bs + (ks * 16) * BLD + wn * 32 + nj * 16, BLD);
#pragma unroll
            for (int mi = 0; mi < 4; ++mi) {
                wmma::fragment<wmma::matrix_a, 16, 16, 16, __half, wmma::row_major> af;
                wmma::load_matrix_sync(af,
                    As + (wm * 64 + mi * 16) * ALD + ks * 16, ALD);
                wmma::mma_sync(acc[mi][0], af, bf[0], acc[mi][0]);
                wmma::mma_sync(acc[mi][1], af, bf[1], acc[mi][1]);
            }
        }
        __syncthreads();
    }

    // ---- epilogue: C -> SMEM (f32), then generic scatter ----
    float* Cs = reinterpret_cast<float*>(smh);
#pragma unroll
    for (int mi = 0; mi < 4; ++mi)
#pragma unroll
        for (int nj = 0; nj < 2; ++nj)
            wmma::store_matrix_sync(Cs + (wm * 64 + mi * 16) * CLD + wn * 32 + nj * 16,
                                    acc[mi][nj], CLD, wmma::mem_row_major);
    __syncthreads();

    for (int f = t; f < 128 * 32; f += 256) {        // 128 rows x 32 float4-cols
        int r  = f >> 5;
        int c4 = (f & 31) * 4;
        float4 v = *reinterpret_cast<const float4*>(Cs + r * CLD + c4);
        int n = nt * 128 + c4;
        v.x += bias[n];  v.y += bias[n + 1];  v.z += bias[n + 2];  v.w += bias[n + 3];
        int m = mt * 128 + r;
        if (MODE == 1) {
            *reinterpret_cast<float4*>(outp + (size_t)m * Dm + n) = v;
        } else {
            int gw = m / 36, vv = m - gw * 36;
            int part = n / 384;
            int pr   = n - part * 384;
            int head = pr / 48, hd = pr - head * 48;
            *reinterpret_cast<float4*>(g_qkv + (size_t)part * PARTsz
                                       + (size_t)gw * (NHm * Vm * HDm)
                                       + (size_t)head * (Vm * HDm)
                                       + (size_t)vv * HDm + hd) = v;
        }
    }
}

// ---------------------------------------------------------------------------
// Attention per (window, head) via wmma tf32, padded 36->48 (R13-proven).
// Output written as fp16 for the proj GEMM.
// ---------------------------------------------------------------------------
__global__ __launch_bounds__(256) void attn_wmma()
{
    __shared__ __align__(16) float qs [48][SLD];   // Q; later reused for O
    __shared__ __align__(16) float kst[48][SLD];   // K^T
    __shared__ __align__(16) float vs [48][SLD];   // V
    __shared__ __align__(16) float ss [48][SLD];   // S, then probs
    __shared__ float pmx[36][6];
    __shared__ float psum[36][6];
    __shared__ float rmax[36];
    __shared__ float rinv[36];
    __shared__ int   rid[36];

    const int t    = threadIdx.x;
    const int wid  = t >> 5;
    const int gw   = blockIdx.x >> 3;
    const int head = blockIdx.x & 7;

    const float* gq = g_qkv + (size_t)gw * (NHm * Vm * HDm) + (size_t)head * (Vm * HDm);
    const float* gk = gq + PARTsz;
    const float* gv = gq + 2 * PARTsz;

    for (int idx = t; idx < 48 * SLD; idx += 256) {
        int r = idx / SLD, c2 = idx - r * SLD;
        qs[r][c2] = 0.f; kst[r][c2] = 0.f; vs[r][c2] = 0.f;
    }
    __syncthreads();

    for (int idx = t; idx < Vm * HDm; idx += 256) {
        int i = idx / 48, d = idx - i * 48;
        qs[i][d]  = tf32r(gq[idx] * ATT_SCALE);
        kst[d][i] = tf32r(gk[idx]);
        vs[i][d]  = tf32r(gv[idx]);
    }
    const int wi = gw & 63;
    const int wh = wi >> 3, ww = wi & 7;
    if (t < 36) {
        int vh = t / 6, vw = t - vh * 6;
        int y  = wh * 6 + vh + 3; if (y  >= 48) y  -= 48;
        int xq = ww * 6 + vw + 3; if (xq >= 48) xq -= 48;
        rid[t] = ((y >= 3) ? 2 : 0) + ((xq >= 3) ? 1 : 0);
    }
    __syncthreads();

    for (int tile = wid; tile < 9; tile += 8) {     // S = Q * K^T
        int mi = tile / 3, ni = tile - mi * 3;
        wmma::fragment<wmma::accumulator, 16, 16, 8, float> sacc;
        wmma::fill_fragment(sacc, 0.0f);
#pragma unroll
        for (int kk = 0; kk < 6; ++kk) {
            wmma::fragment<wmma::matrix_a, 16, 16, 8, wmma::precision::tf32,
                           wmma::row_major> af;
            wmma::fragment<wmma::matrix_b, 16, 16, 8, wmma::precision::tf32,
                           wmma::row_major> bf;
            wmma::load_matrix_sync(af, &qs[mi * 16][kk * 8], SLD);
            wmma::load_matrix_sync(bf, &kst[kk * 8][ni * 16], SLD);
            wmma::mma_sync(sacc, af, bf, sacc);
        }
        wmma::store_matrix_sync(&ss[mi * 16][ni * 16], sacc, SLD, wmma::mem_row_major);
    }
    __syncthreads();

    const int i  = t / 6;
    const int jg = t - i * 6;
    const int j0 = jg * 6;
    float acc[6];

    if (t < 216) {
        int ri = rid[i];
        float m6 = -3.4e38f;
#pragma unroll
        for (int jj = 0; jj < 6; ++jj) {
            float val = ss[i][j0 + jj];
            if (rid[j0 + jj] != ri) val = -1e30f;
            acc[jj] = val;
            m6 = fmaxf(m6, val);
        }
        pmx[i][jg] = m6;
    }
    __syncthreads();
    if (t < 36) {
        float m = pmx[t][0];
#pragma unroll
        for (int g = 1; g < 6; ++g) m = fmaxf(m, pmx[t][g]);
        rmax[t] = m;
    }
    __syncthreads();
    if (t < 216) {
        float m = rmax[i], s = 0.f;
#pragma unroll
        for (int jj = 0; jj < 6; ++jj) {
            acc[jj] = __expf(acc[jj] - m);
            s += acc[jj];
        }
        psum[i][jg] = s;
    }
    __syncthreads();
    if (t < 36) {
        float s = psum[t][0];
#pragma unroll
        for (int g = 1; g < 6; ++g) s += psum[t][g];
        rinv[t] = 1.f / s;
    }
    __syncthreads();
    if (t < 216) {
        float inv = rinv[i];
#pragma unroll
        for (int jj = 0; jj < 6; ++jj)
            ss[i][j0 + jj] = tf32r(acc[jj] * inv);
    }
    __syncthreads();

    for (int tile = wid; tile < 9; tile += 8) {     // O = S * V
        int mi = tile / 3, ni = tile - mi * 3;
        wmma::fragment<wmma::accumulator, 16, 16, 8, float> oacc;
        wmma::fill_fragment(oacc, 0.0f);
#pragma unroll
        for (int kk = 0; kk < 6; ++kk) {
            wmma::fragment<wmma::matrix_a, 16, 16, 8, wmma::precision::tf32,
                           wmma::row_major> af;
            wmma::fragment<wmma::matrix_b, 16, 16, 8, wmma::precision::tf32,
                           wmma::row_major> bf;
            wmma::load_matrix_sync(af, &ss[mi * 16][kk * 8], SLD);
            wmma::load_matrix_sync(bf, &vs[kk * 8][ni * 16], SLD);
            wmma::mma_sync(oacc, af, bf, oacc);
        }
        wmma::store_matrix_sync(&qs[mi * 16][ni * 16], oacc, SLD, wmma::mem_row_major);
    }
    __syncthreads();

    if (t < 216) {
        const int d0 = jg * 8;
        int b  = gw >> 6;
        int vh = i / 6, vw = i - vh * 6;
        int dh = wh * 6 + vh + 3; if (dh >= 48) dh -= 48;   // reverse + roll(+3)
        int dw = ww * 6 + vw + 3; if (dw >= 48) dw -= 48;
        size_t o = ((size_t)(b * 48 + dh) * 48 + dw) * Dm + head * HDm + d0;
        __half2* d2 = reinterpret_cast<__half2*>(&g_att[o]);
#pragma unroll
        for (int dd = 0; dd < 4; ++dd)
            d2[dd] = __floats2half2_rn(qs[i][d0 + dd * 2], qs[i][d0 + dd * 2 + 1]);
    }
}

// ---------------------------------------------------------------------------
extern "C" void kernel_launch(void* const* d_in, const int* in_sizes, int n_in,
                              void* d_out, int out_size)
{
    const float* x     = (const float*)d_in[0];
    const float* wqkv  = (const float*)d_in[1];
    const float* bqkv  = (const float*)d_in[2];
    const float* wproj = (const float*)d_in[3];
    const float* bproj = (const float*)d_in[4];
    float* out = (float*)d_out;

    __half* s_xh; __half* s_wqh; __half* s_wph;
    cudaGetSymbolAddress((void**)&s_xh, g_xh);
    cudaGetSymbolAddress((void**)&s_wqh, g_wqh);
    cudaGetSymbolAddress((void**)&s_wph, g_wph);
    cudaFuncSetAttribute(gemm_hmma<0>, cudaFuncAttributeMaxDynamicSharedMemorySize, SMEM_BYTES);
    cudaFuncSetAttribute(gemm_hmma<1>, cudaFuncAttributeMaxDynamicSharedMemorySize, SMEM_BYTES);

    const int nx = Tm * Dm / 4, nwq = 384 * TDm / 4, nwp = 384 * Dm / 4;
    prep_half<<<(nx  + 255) / 256, 256>>>((const float4*)x,     s_xh,  nx);
    prep_half<<<(nwq + 255) / 256, 256>>>((const float4*)wqkv,  s_wqh, nwq);
    prep_half<<<(nwp + 255) / 256, 256>>>((const float4*)wproj, s_wph, nwp);

    gemm_hmma<0><<<dim3(9, 576), 256, SMEM_BYTES>>>(bqkv, nullptr, TDm);
    attn_wmma<<<GWm * NHm, 256>>>();
    gemm_hmma<1><<<dim3(3, 576), 256, SMEM_BYTES>>>(bproj, out, Dm);
}

// round 17
// speedup vs baseline: 3.0810x; 1.1504x over previous
#include <cuda_runtime.h>
#include <cuda_fp16.h>
#include <cstdint>
#include <mma.h>

using namespace nvcuda;

// ---------------------------------------------------------------------------
// SW-MSA on GB300 (compute_103-portable).
// GEMMs: wmma m16n16k16 FP16 (f32 acc), K-chunks of 64, 3-stage cp.async,
//        ONE barrier per chunk, 2 CTAs/SM.
// Attention: wmma FP16 per (window,head), padded 36->48; softmax in f32.
// q/k/v intermediate stored as fp16 (halves the g_qkv round-trip).
// ---------------------------------------------------------------------------

namespace {
constexpr int Dm  = 384;
constexpr int TDm = 1152;
constexpr int NHm = 8;
constexpr int HDm = 48;
constexpr int Vm  = 36;
constexpr int GWm = 2048;
constexpr int Tm  = 73728;
constexpr float ATT_SCALE = 0.14433756729740643f;   // 48^-0.5

constexpr int KCH  = 64;        // K per chunk (halfs)
constexpr int NCH  = 6;         // 384 / 64
constexpr int ALD  = 72;        // A stage ld in halfs
constexpr int BLD  = 136;       // B stage ld in halfs
constexpr int CLD  = 132;       // C smem tile ld (floats)
constexpr int AST  = 128 * ALD;             // 9216 halfs
constexpr int BST  = 64 * BLD;              // 8704 halfs
constexpr int STG  = AST + BST;             // 17920 halfs = 35840 B
constexpr int NSTG = 3;
constexpr int SMEM_BYTES = NSTG * STG * 2;  // 107520 B (C tile 67584 B reuses)
constexpr size_t PARTsz = (size_t)GWm * NHm * Vm * HDm;

constexpr int SLH = 56;         // attn half-tile ld (48 + 8)
constexpr int SLF = 52;         // attn float S/O ld
}

// static device scratch (allocation-free per harness rules)
__device__ __half g_xh[(size_t)Tm * Dm];            // x as fp16
__device__ __half g_wqh[(size_t)384 * TDm];         // w_qkv as fp16
__device__ __half g_wph[(size_t)384 * Dm];          // w_proj as fp16
__device__ __half g_qkvh[3 * PARTsz];               // [part][win][head][v][hd] fp16
__device__ __half g_att[(size_t)Tm * Dm];           // attn out as fp16

// ---------------- helpers ----------------
__device__ __forceinline__ uint32_t smem_u32(const void* p) {
    uint32_t a;
    asm("{ .reg .u64 t; cvta.to.shared.u64 t, %1; cvt.u32.u64 %0, t; }"
        : "=r"(a) : "l"(p));
    return a;
}
__device__ __forceinline__ void cpa16(uint32_t dst, const void* src) {
    asm volatile("cp.async.cg.shared.global [%0], [%1], 16;" :: "r"(dst), "l"(src));
}
__device__ __forceinline__ size_t gather_off(int m) {   // roll(-3,-3) + win partition
    int gw = m / 36, v = m - gw * 36;
    int b  = gw >> 6, wi = gw & 63;
    int wh = wi >> 3, ww = wi & 7;
    int vh = v / 6,  vw = v - vh * 6;
    int sh = wh * 6 + vh + 3; if (sh >= 48) sh -= 48;
    int sw = ww * 6 + vw + 3; if (sw >= 48) sw -= 48;
    return (size_t)((b * 48 + sh) * 48 + sw) * Dm;
}

// ---------------------------------------------------------------------------
// prep: f32 -> f16
// ---------------------------------------------------------------------------
__global__ __launch_bounds__(256) void prep_half(const float4* __restrict__ src,
                                                 __half* __restrict__ dst, int n4)
{
    int i = blockIdx.x * 256 + threadIdx.x;
    if (i < n4) {
        float4 v = src[i];
        __half2* d2 = reinterpret_cast<__half2*>(dst + (size_t)i * 4);
        d2[0] = __floats2half2_rn(v.x, v.y);
        d2[1] = __floats2half2_rn(v.z, v.w);
    }
}

// ---------------------------------------------------------------------------
// wmma fp16 GEMM. CTA 128x128, 8 warps 2x4, warp tile 64x32, K chunks of 64,
// 3-stage cp.async, ONE barrier per chunk, 2 CTAs/SM.
// MODE 0: A = g_xh (roll/window gather), W = g_wqh -> scatter half into g_qkvh.
// MODE 1: A = g_att (row-major half),    W = g_wph -> f32 row-major into outp.
// ---------------------------------------------------------------------------
template<int MODE>
__global__ __launch_bounds__(256, 2) void gemm_hmma(const float* __restrict__ bias,
                                                    float* __restrict__ outp, int N)
{
    extern __shared__ __half smh[];
    const int t = threadIdx.x, wid = t >> 5;
    const int wm = wid >> 2, wn = wid & 3;
    const int mt = blockIdx.y, nt = blockIdx.x;

    const __half* Abase = (MODE == 0) ? g_xh : g_att;
    const __half* W     = (MODE == 0) ? g_wqh : g_wph;

    const int ar = t >> 1, ah = (t & 1) * 32;
    size_t aoff = (MODE == 0) ? gather_off(mt * 128 + ar)
                              : (size_t)(mt * 128 + ar) * Dm;
    const __half* asrc = Abase + aoff + ah;
    const int bk = t >> 2, bs = (t & 3) * 32;
    const __half* bsrc = W + (size_t)bk * N + nt * 128 + bs;

    const uint32_t sa0 = smem_u32(smh + ar * ALD + ah);
    const uint32_t sb0 = smem_u32(smh + AST + bk * BLD + bs);

    auto stage_cp = [&](int c, int s) {
        uint32_t sa = sa0 + (uint32_t)s * (STG * 2);
        uint32_t sb = sb0 + (uint32_t)s * (STG * 2);
        const __half* ap = asrc + c * KCH;
        const __half* bp = bsrc + (size_t)c * KCH * N;
#pragma unroll
        for (int j = 0; j < 4; ++j) {
            cpa16(sa + j * 16u, ap + j * 8);
            cpa16(sb + j * 16u, bp + j * 8);
        }
        asm volatile("cp.async.commit_group;");
    };

    wmma::fragment<wmma::accumulator, 16, 16, 16, float> acc[4][2];
#pragma unroll
    for (int mi = 0; mi < 4; ++mi)
#pragma unroll
        for (int nj = 0; nj < 2; ++nj)
            wmma::fill_fragment(acc[mi][nj], 0.0f);

    stage_cp(0, 0);
    stage_cp(1, 1);

    int s_cur = 0, s_pf = 2;
    for (int c = 0; c < NCH; ++c) {
        if (c + 1 < NCH) {
            asm volatile("cp.async.wait_group 1;" ::: "memory");
        } else {
            asm volatile("cp.async.wait_group 0;" ::: "memory");
        }
        __syncthreads();      // single barrier: chunk c visible AND all warps
                              // done reading stage (c-1) -> safe to restage it
        if (c + 2 < NCH) {
            stage_cp(c + 2, s_pf);
            if (++s_pf == NSTG) s_pf = 0;
        }

        const __half* As = smh + s_cur * STG;
        const __half* Bs = As + AST;
        if (++s_cur == NSTG) s_cur = 0;
#pragma unroll
        for (int ks = 0; ks < 4; ++ks) {
            wmma::fragment<wmma::matrix_b, 16, 16, 16, __half, wmma::row_major> bf[2];
#pragma unroll
            for (int nj = 0; nj < 2; ++nj)
                wmma::load_matrix_sync(bf[nj],
                    Bs + (ks * 16) * BLD + wn * 32 + nj * 16, BLD);
#pragma unroll
            for (int mi = 0; mi < 4; ++mi) {
                wmma::fragment<wmma::matrix_a, 16, 16, 16, __half, wmma::row_major> af;
                wmma::load_matrix_sync(af,
                    As + (wm * 64 + mi * 16) * ALD + ks * 16, ALD);
                wmma::mma_sync(acc[mi][0], af, bf[0], acc[mi][0]);
                wmma::mma_sync(acc[mi][1], af, bf[1], acc[mi][1]);
            }
        }
    }
    __syncthreads();   // all compute done before Cs overwrites stages 0/1

    float* Cs = reinterpret_cast<float*>(smh);
#pragma unroll
    for (int mi = 0; mi < 4; ++mi)
#pragma unroll
        for (int nj = 0; nj < 2; ++nj)
            wmma::store_matrix_sync(Cs + (wm * 64 + mi * 16) * CLD + wn * 32 + nj * 16,
                                    acc[mi][nj], CLD, wmma::mem_row_major);
    __syncthreads();

    for (int f = t; f < 128 * 32; f += 256) {
        int r  = f >> 5;
        int c4 = (f & 31) * 4;
        float4 v = *reinterpret_cast<const float4*>(Cs + r * CLD + c4);
        int n = nt * 128 + c4;
        v.x += bias[n];  v.y += bias[n + 1];  v.z += bias[n + 2];  v.w += bias[n + 3];
        int m = mt * 128 + r;
        if (MODE == 1) {
            *reinterpret_cast<float4*>(outp + (size_t)m * Dm + n) = v;
        } else {
            int gw = m / 36, vv = m - gw * 36;
            int part = n / 384;
            int pr   = n - part * 384;
            int head = pr / 48, hd = pr - head * 48;
            __half2 h01 = __floats2half2_rn(v.x, v.y);
            __half2 h23 = __floats2half2_rn(v.z, v.w);
            __half2* dst = reinterpret_cast<__half2*>(
                g_qkvh + (size_t)part * PARTsz
                + (size_t)gw * (NHm * Vm * HDm)
                + (size_t)head * (Vm * HDm) + (size_t)vv * HDm + hd);
            dst[0] = h01; dst[1] = h23;
        }
    }
}

// ---------------------------------------------------------------------------
// Attention per (window, head) via wmma FP16, padded 36->48.
// S = Q*K^T and O = P*V as 9 warp-tiles x 3 k-steps. Softmax in f32.
// ---------------------------------------------------------------------------
__global__ __launch_bounds__(256) void attn_hmma()
{
    __shared__ __align__(16) __half qh [48][SLH];   // Q (scaled)
    __shared__ __align__(16) __half kth[48][SLH];   // K^T [hd][tok]
    __shared__ __align__(16) __half vh [48][SLH];   // V [tok][hd]
    __shared__ __align__(16) __half ph [48][SLH];   // probs
    __shared__ __align__(16) float  ss [48][SLF];   // S scores, then O
    __shared__ float pmx[36][6];
    __shared__ float psum[36][6];
    __shared__ float rmax[36];
    __shared__ float rinv[36];
    __shared__ int   rid[36];

    const int t    = threadIdx.x;
    const int wid  = t >> 5;
    const int gw   = blockIdx.x >> 3;
    const int head = blockIdx.x & 7;

    const __half* gq = g_qkvh + (size_t)gw * (NHm * Vm * HDm) + (size_t)head * (Vm * HDm);
    const __half* gk = gq + PARTsz;
    const __half* gv = gq + 2 * PARTsz;

    // zero pads (qh/kth/vh/ph fully; live regions overwritten below)
    for (int idx = t; idx < 48 * SLH; idx += 256) {
        int r = idx / SLH, c2 = idx - r * SLH;
        qh[r][c2] = __half(0.f); kth[r][c2] = __half(0.f);
        vh[r][c2] = __half(0.f); ph[r][c2] = __half(0.f);
    }
    __syncthreads();

    for (int idx = t; idx < Vm * HDm; idx += 256) {
        int i = idx / 48, d = idx - i * 48;
        qh[i][d]  = __float2half(__half2float(gq[idx]) * ATT_SCALE);
        kth[d][i] = gk[idx];
        vh[i][d]  = gv[idx];
    }
    const int wi = gw & 63;
    const int wh = wi >> 3, ww = wi & 7;
    if (t < 36) {
        int vh2 = t / 6, vw = t - vh2 * 6;
        int y  = wh * 6 + vh2 + 3; if (y  >= 48) y  -= 48;
        int xq = ww * 6 + vw  + 3; if (xq >= 48) xq -= 48;
        rid[t] = ((y >= 3) ? 2 : 0) + ((xq >= 3) ? 1 : 0);
    }
    __syncthreads();

    // ---- S = Q * K^T (48x48x48, fp16): 9 tiles over 8 warps ----
    for (int tile = wid; tile < 9; tile += 8) {
        int mi = tile / 3, ni = tile - mi * 3;
        wmma::fragment<wmma::accumulator, 16, 16, 16, float> sacc;
        wmma::fill_fragment(sacc, 0.0f);
#pragma unroll
        for (int kk = 0; kk < 3; ++kk) {
            wmma::fragment<wmma::matrix_a, 16, 16, 16, __half, wmma::row_major> af;
            wmma::fragment<wmma::matrix_b, 16, 16, 16, __half, wmma::row_major> bf;
            wmma::load_matrix_sync(af, &qh[mi * 16][kk * 16], SLH);
            wmma::load_matrix_sync(bf, &kth[kk * 16][ni * 16], SLH);
            wmma::mma_sync(sacc, af, bf, sacc);
        }
        wmma::store_matrix_sync(&ss[mi * 16][ni * 16], sacc, SLF, wmma::mem_row_major);
    }
    __syncthreads();

    // ---- mask + softmax on the 36x36 live block (f32) ----
    const int i  = t / 6;
    const int jg = t - i * 6;
    const int j0 = jg * 6;
    float acc[6];

    if (t < 216) {
        int ri = rid[i];
        float m6 = -3.4e38f;
#pragma unroll
        for (int jj = 0; jj < 6; ++jj) {
            float val = ss[i][j0 + jj];
            if (rid[j0 + jj] != ri) val = -1e30f;
            acc[jj] = val;
            m6 = fmaxf(m6, val);
        }
        pmx[i][jg] = m6;
    }
    __syncthreads();
    if (t < 36) {
        float m = pmx[t][0];
#pragma unroll
        for (int g = 1; g < 6; ++g) m = fmaxf(m, pmx[t][g]);
        rmax[t] = m;
    }
    __syncthreads();
    if (t < 216) {
        float m = rmax[i], s = 0.f;
#pragma unroll
        for (int jj = 0; jj < 6; ++jj) {
            acc[jj] = __expf(acc[jj] - m);
            s += acc[jj];
        }
        psum[i][jg] = s;
    }
    __syncthreads();
    if (t < 36) {
        float s = psum[t][0];
#pragma unroll
        for (int g = 1; g < 6; ++g) s += psum[t][g];
        rinv[t] = 1.f / s;
    }
    __syncthreads();
    if (t < 216) {
        float inv = rinv[i];
#pragma unroll
        for (int jj = 0; jj < 6; ++jj)
            ph[i][j0 + jj] = __float2half(acc[jj] * inv);   // pads stay 0
    }
    __syncthreads();

    // ---- O = P * V (48x48x48, fp16) into ss ----
    for (int tile = wid; tile < 9; tile += 8) {
        int mi = tile / 3, ni = tile - mi * 3;
        wmma::fragment<wmma::accumulator, 16, 16, 16, float> oacc;
        wmma::fill_fragment(oacc, 0.0f);
#pragma unroll
        for (int kk = 0; kk < 3; ++kk) {
            wmma::fragment<wmma::matrix_a, 16, 16, 16, __half, wmma::row_major> af;
            wmma::fragment<wmma::matrix_b, 16, 16, 16, __half, wmma::row_major> bf;
            wmma::load_matrix_sync(af, &ph[mi * 16][kk * 16], SLH);
            wmma::load_matrix_sync(bf, &vh[kk * 16][ni * 16], SLH);
            wmma::mma_sync(oacc, af, bf, oacc);
        }
        wmma::store_matrix_sync(&ss[mi * 16][ni * 16], oacc, SLF, wmma::mem_row_major);
    }
    __syncthreads();

    // ---- write out (half) with reverse + roll(+3) ----
    if (t < 216) {
        const int d0 = jg * 8;
        int b  = gw >> 6;
        int vh2 = i / 6, vw = i - vh2 * 6;
        int dh = wh * 6 + vh2 + 3; if (dh >= 48) dh -= 48;
        int dw = ww * 6 + vw  + 3; if (dw >= 48) dw -= 48;
        size_t o = ((size_t)(b * 48 + dh) * 48 + dw) * Dm + head * HDm + d0;
        __half2* d2 = reinterpret_cast<__half2*>(&g_att[o]);
#pragma unroll
        for (int dd = 0; dd < 4; ++dd)
            d2[dd] = __floats2half2_rn(ss[i][d0 + dd * 2], ss[i][d0 + dd * 2 + 1]);
    }
}

// ---------------------------------------------------------------------------
extern "C" void kernel_launch(void* const* d_in, const int* in_sizes, int n_in,
                              void* d_out, int out_size)
{
    const float* x     = (const float*)d_in[0];
    const float* wqkv  = (const float*)d_in[1];
    const float* bqkv  = (const float*)d_in[2];
    const float* wproj = (const float*)d_in[3];
    const float* bproj = (const float*)d_in[4];
    float* out = (float*)d_out;

    __half* s_xh; __half* s_wqh; __half* s_wph;
    cudaGetSymbolAddress((void**)&s_xh, g_xh);
    cudaGetSymbolAddress((void**)&s_wqh, g_wqh);
    cudaGetSymbolAddress((void**)&s_wph, g_wph);
    cudaFuncSetAttribute(gemm_hmma<0>, cudaFuncAttributeMaxDynamicSharedMemorySize, SMEM_BYTES);
    cudaFuncSetAttribute(gemm_hmma<1>, cudaFuncAttributeMaxDynamicSharedMemorySize, SMEM_BYTES);

    const int nx = Tm * Dm / 4, nwq = 384 * TDm / 4, nwp = 384 * Dm / 4;
    prep_half<<<(nx  + 255) / 256, 256>>>((const float4*)x,     s_xh,  nx);
    prep_half<<<(nwq + 255) / 256, 256>>>((const float4*)wqkv,  s_wqh, nwq);
    prep_half<<<(nwp + 255) / 256, 256>>>((const float4*)wproj, s_wph, nwp);

    gemm_hmma<0><<<dim3(9, 576), 256, SMEM_BYTES>>>(bqkv, nullptr, TDm);
    attn_hmma<<<GWm * NHm, 256>>>();
    gemm_hmma<1><<<dim3(3, 576), 256, SMEM_BYTES>>>(bproj, out, Dm);
}